// round 6
// baseline (speedup 1.0000x reference)
#include <cuda_runtime.h>
#include <math.h>

#define B_SZ 4
#define N_PTS 8192
#define KNN 20
#define NCH 16
#define TILE 1024                          // points per staged tile
#define THREADS 128
#define SPLIT 4                            // one split per warp
#define QPB (THREADS / SPLIT)              // 32 queries per block
#define DQ 24                              // per-lane buffer depth
#define NBLK ((B_SZ * N_PTS) / QPB)        // 1024 knn blocks

typedef unsigned long long u64;

__device__ float  g_dmax[B_SZ * N_PTS];
__device__ double g_p1[NBLK];
__device__ double g_p2[NBLK];
__device__ float  g_mv[2];

__device__ __forceinline__ u64 pack2(float a, float b) {
    u64 d; asm("mov.b64 %0, {%1, %2};" : "=l"(d) : "f"(a), "f"(b)); return d;
}
__device__ __forceinline__ u64 ffma2(u64 a, u64 b, u64 c) {
    u64 d; asm("fma.rn.f32x2 %0, %1, %2, %3;" : "=l"(d) : "l"(a), "l"(b), "l"(c));
    return d;
}
__device__ __forceinline__ void unpack2(u64 d, float& a, float& b) {
    asm("mov.b64 {%0, %1}, %2;" : "=f"(a), "=f"(b) : "l"(d));
}

__device__ __forceinline__ void insert1(float (&r)[KNN], float v) {
#pragma unroll
    for (int k = KNN - 1; k >= 1; k--)
        r[k] = fminf(r[k], fmaxf(r[k - 1], v));
    r[0] = fminf(r[0], v);
}

__device__ __forceinline__ void drain_buf(float (&r)[KNN], const float* mybuf,
                                          int& cnt, float& r19) {
    const float INF = __int_as_float(0x7f800000);
    int jmax = (int)__reduce_max_sync(0xffffffffu, (unsigned)cnt);
    for (int j = 0; j < jmax; j++) {            // warp-uniform loop
        float v = mybuf[j * 32];                // lane-strided: conflict-free
        v = (j < cnt) ? v : INF;
        insert1(r, v);
    }
    cnt = 0;
    r19 = r[KNN - 1];
}

__global__ __launch_bounds__(THREADS, 8) void knn_kernel(const float* __restrict__ x) {
    // pair-packed tile: pair pi -> sh4[2*pi] = (x0,x1,y0,y1), sh4[2*pi+1] = (z0,z1,w0,w1)
    __shared__ float4 sh4[TILE];                      // 16 KB (TILE/2 pairs)
    __shared__ float  buf[(THREADS / 32) * 32 * DQ];  // 12 KB; reused for merge

    const int warp = threadIdx.x >> 5, lane = threadIdx.x & 31;
    float* mybuf = buf + warp * 32 * DQ + lane;       // slot j -> mybuf[j*32]

    const int ql = lane;                              // local query 0..31
    const int s  = warp;                              // split 0..3

    const int blocks_per_batch = N_PTS / QPB;         // 256
    const int b = blockIdx.x / blocks_per_batch;
    const int n = (blockIdx.x % blocks_per_batch) * QPB + ql;

    const float* xb = x + (size_t)b * 3 * N_PTS;
    const float qx = xb[n];
    const float qy = xb[N_PTS + n];
    const float qz = xb[2 * N_PTS + n];
    const float qsq = fmaf(qx, qx, fmaf(qy, qy, qz * qz));
    // fold -2 into query: e = |p|^2 - 2 q.p = d2 - qsq (order-preserving)
    const u64 qx2 = pack2(-2.f * qx, -2.f * qx);
    const u64 qy2 = pack2(-2.f * qy, -2.f * qy);
    const u64 qz2 = pack2(-2.f * qz, -2.f * qz);

    const float INF = __int_as_float(0x7f800000);
    float r[KNN];
#pragma unroll
    for (int k = 0; k < KNN; k++) r[k] = INF;
    float r19 = INF;   // stale threshold, refreshed at drains (conservative)
    int cnt = 0;

    for (int t = 0; t < N_PTS; t += TILE) {
        __syncthreads();
        {   // stage 8 consecutive points per thread as 4 packed pairs
            int base = t + threadIdx.x * 8;
            const float4* X = (const float4*)(xb + base);
            const float4* Y = (const float4*)(xb + N_PTS + base);
            const float4* Z = (const float4*)(xb + 2 * N_PTS + base);
            float4 X0 = X[0], X1 = X[1], Y0 = Y[0], Y1 = Y[1], Z0 = Z[0], Z1 = Z[1];
            float xs[8] = {X0.x, X0.y, X0.z, X0.w, X1.x, X1.y, X1.z, X1.w};
            float ys[8] = {Y0.x, Y0.y, Y0.z, Y0.w, Y1.x, Y1.y, Y1.z, Y1.w};
            float zs[8] = {Z0.x, Z0.y, Z0.z, Z0.w, Z1.x, Z1.y, Z1.z, Z1.w};
            float ws[8];
#pragma unroll
            for (int i = 0; i < 8; i++)
                ws[i] = fmaf(xs[i], xs[i], fmaf(ys[i], ys[i], zs[i] * zs[i]));
#pragma unroll
            for (int m = 0; m < 4; m++) {
                int pl = threadIdx.x * 4 + m;
                sh4[2 * pl]     = make_float4(xs[2*m], xs[2*m+1], ys[2*m], ys[2*m+1]);
                sh4[2 * pl + 1] = make_float4(zs[2*m], zs[2*m+1], ws[2*m], ws[2*m+1]);
            }
        }
        __syncthreads();

        const ulonglong2* shp = (const ulonglong2*)sh4;   // [pair]: {xx,yy},{zz,ww}
        for (int j = 0; j < TILE / 2 / SPLIT; j += 4) {   // 4 pairs = 8 candidates
            if (__any_sync(0xffffffffu, cnt >= DQ - 8))
                drain_buf(r, mybuf, cnt, r19);
#pragma unroll
            for (int u = 0; u < 4; u++) {
                int pi = s + ((j + u) << 2);              // warp-uniform -> broadcast
                ulonglong2 A = shp[2 * pi];               // (x0,x1),(y0,y1)
                ulonglong2 C = shp[2 * pi + 1];           // (z0,z1),(w0,w1)
                u64 e2 = ffma2(qx2, A.x, ffma2(qy2, A.y, ffma2(qz2, C.x, C.y)));
                float e0, e1; unpack2(e2, e0, e1);
                bool q0 = e0 < r19;
                mybuf[cnt * 32] = e0; cnt += (int)q0;     // commits only if q0
                bool q1 = e1 < r19;
                mybuf[cnt * 32] = e1; cnt += (int)q1;
            }
        }
    }
    drain_buf(r, mybuf, cnt, r19);        // tail drain

    // ---- merge the 4 split lists per query (exact top-20 of union) ----
    __syncthreads();                       // buf now free -> merge storage
    float* mbuf = buf;                     // [(s-1)*32 + ql]*21 + k (pad 21: no conflicts)
    if (s >= 1) {
#pragma unroll
        for (int k = 0; k < KNN; k++)
            mbuf[((s - 1) * QPB + ql) * 21 + k] = r[k];
    }
    __syncthreads();

    if (s == 0) {
        for (int m = 0; m < SPLIT - 1; m++)
#pragma unroll
            for (int k = 0; k < KNN; k++)
                insert1(r, mbuf[(m * QPB + ql) * 21 + k]);

        // finalize: back to d2-space, clamp, sqrt, stats in double
        double s1 = 0.0, s2 = 0.0;
#pragma unroll
        for (int k = 0; k < KNN; k++) {
            float d2 = fmaxf(r[k] + qsq, 0.f);
            float d = sqrtf(d2);
            s1 += (double)d;
            s2 += (double)d2;
        }
        g_dmax[b * N_PTS + n] = sqrtf(fmaxf(r[KNN - 1] + qsq, 0.f));

#pragma unroll
        for (int o = 16; o > 0; o >>= 1) {
            s1 += __shfl_xor_sync(0xffffffffu, s1, o);
            s2 += __shfl_xor_sync(0xffffffffu, s2, o);
        }
        if (lane == 0) {
            g_p1[blockIdx.x] = s1;
            g_p2[blockIdx.x] = s2;
        }
    }
}

__global__ void stats_kernel() {
    __shared__ double sr1[4], sr2[4];
    int t = threadIdx.x;
    double v1 = 0.0, v2 = 0.0;
#pragma unroll
    for (int i = 0; i < NBLK / 128; i++) {
        v1 += g_p1[t + i * 128];
        v2 += g_p2[t + i * 128];
    }
#pragma unroll
    for (int o = 16; o > 0; o >>= 1) {
        v1 += __shfl_xor_sync(0xffffffffu, v1, o);
        v2 += __shfl_xor_sync(0xffffffffu, v2, o);
    }
    if ((t & 31) == 0) { sr1[t >> 5] = v1; sr2[t >> 5] = v2; }
    __syncthreads();
    if (t == 0) {
        double s1 = sr1[0] + sr1[1] + sr1[2] + sr1[3];
        double s2 = sr2[0] + sr2[1] + sr2[2] + sr2[3];
        const double M = (double)(B_SZ * N_PTS * KNN);
        double m = s1 / M;
        double var = s2 / M - m * m;
        if (var < 0.0) var = 0.0;
        g_mv[0] = (float)m;
        g_mv[1] = (float)var;
    }
}

__global__ __launch_bounds__(256) void out_kernel(const float* __restrict__ conv_w,
                                                  const float* __restrict__ gamma,
                                                  const float* __restrict__ beta,
                                                  float* __restrict__ out) {
    __shared__ float s_s[NCH], s_t[NCH];
    if (threadIdx.x < NCH) {
        int c = threadIdx.x;
        float m = g_mv[0];
        float v = g_mv[1];
        float w = conv_w[c];
        float s = gamma[c] * w * rsqrtf(fmaf(w * w, v, 1e-5f));
        s_s[c] = s;
        s_t[c] = beta[c] - s * m;   // conv_b cancels in training-mode BN
    }
    __syncthreads();

    int q = blockIdx.x * blockDim.x + threadIdx.x;
    int b = q / N_PTS, n = q % N_PTS;
    float dmax = g_dmax[q];
#pragma unroll
    for (int c = 0; c < NCH; c++) {
        float s = s_s[c];
        float knn = (s >= 0.f) ? dmax : 0.f;  // min knn = 0 (self-distance)
        float y = fmaf(s, knn, s_t[c]);
        y = (y >= 0.f) ? y : 0.2f * y;        // LeakyReLU commutes with max_k
        out[((size_t)b * NCH + c) * N_PTS + n] = y;
    }
}

extern "C" void kernel_launch(void* const* d_in, const int* in_sizes, int n_in,
                              void* d_out, int out_size) {
    const float* x      = (const float*)d_in[0];
    const float* conv_w = (const float*)d_in[1];
    const float* gamma  = (const float*)d_in[3];
    const float* beta   = (const float*)d_in[4];
    float* out = (float*)d_out;

    knn_kernel<<<NBLK, THREADS>>>(x);
    stats_kernel<<<1, 128>>>();
    out_kernel<<<(B_SZ * N_PTS) / 256, 256>>>(conv_w, gamma, beta, out);
}

// round 7
// speedup vs baseline: 1.0559x; 1.0559x over previous
#include <cuda_runtime.h>
#include <math.h>

#define B_SZ 4
#define N_PTS 8192
#define KNN 20
#define NCH 16
#define TILE 1024
#define THREADS 256
#define SPLIT 4
#define QPB (THREADS / SPLIT)              // 64 queries per block
#define DQ 32                              // per-lane buffer depth
#define NBLK ((B_SZ * N_PTS) / QPB)        // 512 knn blocks

__device__ float  g_dmax[B_SZ * N_PTS];
__device__ double g_p1[NBLK];
__device__ double g_p2[NBLK];
__device__ float  g_mv[2];

__device__ __forceinline__ void insert1(float (&r)[KNN], float v) {
#pragma unroll
    for (int k = KNN - 1; k >= 1; k--)
        r[k] = fminf(r[k], fmaxf(r[k - 1], v));
    r[0] = fminf(r[0], v);
}

__device__ __forceinline__ void drain_buf(float (&r)[KNN], const float* mybuf,
                                          int& cnt, float& r19) {
    const float INF = __int_as_float(0x7f800000);
    int jmax = (int)__reduce_max_sync(0xffffffffu, (unsigned)cnt);
    for (int j = 0; j < jmax; j++) {            // warp-uniform loop
        float v = mybuf[j * 32];                // lane-strided: conflict-free
        v = (j < cnt) ? v : INF;
        insert1(r, v);
    }
    cnt = 0;
    r19 = r[KNN - 1];
}

__global__ __launch_bounds__(THREADS, 4) void knn_kernel(const float* __restrict__ x) {
    __shared__ float4 sh[TILE];                       // 16 KB
    __shared__ float  buf[(THREADS / 32) * 32 * DQ];  // 32 KB; reused for merge
    __shared__ double red1[2], red2[2];

    const int warp = threadIdx.x >> 5, lane = threadIdx.x & 31;
    float* mybuf = buf + warp * 32 * DQ + lane;       // slot j -> mybuf[j*32]

    const int ql = threadIdx.x & (QPB - 1);           // local query 0..63
    const int s  = threadIdx.x >> 6;                  // split 0..3 (warp-uniform)

    const int blocks_per_batch = N_PTS / QPB;         // 128
    const int b = blockIdx.x / blocks_per_batch;
    const int n = (blockIdx.x % blocks_per_batch) * QPB + ql;

    const float* xb = x + (size_t)b * 3 * N_PTS;
    const float qx = xb[n];
    const float qy = xb[N_PTS + n];
    const float qz = xb[2 * N_PTS + n];
    const float qsq = fmaf(qx, qx, fmaf(qy, qy, qz * qz));

    // top-20 in e-space: e = |p|^2 - 2 q.p = d2 - qsq (order-preserving)
    const float INF = __int_as_float(0x7f800000);
    float r[KNN];
#pragma unroll
    for (int k = 0; k < KNN; k++) r[k] = INF;
    float r19 = INF;   // stale threshold, refreshed at drains (conservative)
    int cnt = 0;

    for (int t = 0; t < N_PTS; t += TILE) {
        __syncthreads();
        for (int i = threadIdx.x; i < TILE; i += THREADS) {
            float px = xb[t + i];
            float py = xb[N_PTS + t + i];
            float pz = xb[2 * N_PTS + t + i];
            float psq = fmaf(px, px, fmaf(py, py, pz * pz));
            sh[i] = make_float4(-2.f * px, -2.f * py, -2.f * pz, psq);
        }
        __syncthreads();

        const float4* shs = sh + s;        // split s scans i ≡ s (mod 4)
        int jstart = 0;
        if (t == 0) {
            // seed: first 32 candidates inserted unconditionally -> real r19,
            // kills the all-qualify burst that flooded the early drains
            for (int j = 0; j < 32; j++) {
                float4 p = shs[j << 2];
                float e = fmaf(qx, p.x, fmaf(qy, p.y, fmaf(qz, p.z, p.w)));
                insert1(r, e);
            }
            r19 = r[KNN - 1];
            jstart = 32;
        }
        for (int j = jstart; j < TILE / SPLIT; j += 8) {
            if (__any_sync(0xffffffffu, cnt >= DQ - 8))
                drain_buf(r, mybuf, cnt, r19);
#pragma unroll
            for (int u = 0; u < 8; u++) {
                float4 p = shs[(j + u) << 2];   // warp-uniform -> broadcast
                float e = fmaf(qx, p.x, fmaf(qy, p.y, fmaf(qz, p.z, p.w)));
                bool q = e < r19;
                mybuf[cnt * 32] = e;      // unconditional; commits only if q
                cnt += (int)q;
            }
        }
    }
    drain_buf(r, mybuf, cnt, r19);        // tail drain

    // ---- merge the 4 split lists per query (exact top-20 of union) ----
    __syncthreads();                       // buf now free -> merge storage
    float* mbuf = buf;                     // [(s-1)*64 + ql]*21 + k (pad 21)
    if (s >= 1) {
#pragma unroll
        for (int k = 0; k < KNN; k++)
            mbuf[((s - 1) * QPB + ql) * 21 + k] = r[k];
    }
    __syncthreads();

    if (s == 0) {
        for (int m = 0; m < SPLIT - 1; m++)
#pragma unroll
            for (int k = 0; k < KNN; k++)
                insert1(r, mbuf[(m * QPB + ql) * 21 + k]);

        // finalize: back to d2-space, clamp, sqrt, stats in double
        double s1 = 0.0, s2 = 0.0;
#pragma unroll
        for (int k = 0; k < KNN; k++) {
            float d2 = fmaxf(r[k] + qsq, 0.f);
            float d = sqrtf(d2);
            s1 += (double)d;
            s2 += (double)d2;
        }
        g_dmax[b * N_PTS + n] = sqrtf(fmaxf(r[KNN - 1] + qsq, 0.f));

#pragma unroll
        for (int o = 16; o > 0; o >>= 1) {
            s1 += __shfl_xor_sync(0xffffffffu, s1, o);
            s2 += __shfl_xor_sync(0xffffffffu, s2, o);
        }
        if (lane == 0) { red1[warp] = s1; red2[warp] = s2; }  // warps 0,1 only
    }
    __syncthreads();
    if (threadIdx.x == 0) {
        g_p1[blockIdx.x] = red1[0] + red1[1];
        g_p2[blockIdx.x] = red2[0] + red2[1];
    }
}

__global__ void stats_kernel() {
    __shared__ double sr1[4], sr2[4];
    int t = threadIdx.x;
    double v1 = 0.0, v2 = 0.0;
#pragma unroll
    for (int i = 0; i < NBLK / 128; i++) {
        v1 += g_p1[t + i * 128];
        v2 += g_p2[t + i * 128];
    }
#pragma unroll
    for (int o = 16; o > 0; o >>= 1) {
        v1 += __shfl_xor_sync(0xffffffffu, v1, o);
        v2 += __shfl_xor_sync(0xffffffffu, v2, o);
    }
    if ((t & 31) == 0) { sr1[t >> 5] = v1; sr2[t >> 5] = v2; }
    __syncthreads();
    if (t == 0) {
        double s1 = sr1[0] + sr1[1] + sr1[2] + sr1[3];
        double s2 = sr2[0] + sr2[1] + sr2[2] + sr2[3];
        const double M = (double)(B_SZ * N_PTS * KNN);
        double m = s1 / M;
        double var = s2 / M - m * m;
        if (var < 0.0) var = 0.0;
        g_mv[0] = (float)m;
        g_mv[1] = (float)var;
    }
}

__global__ __launch_bounds__(256) void out_kernel(const float* __restrict__ conv_w,
                                                  const float* __restrict__ gamma,
                                                  const float* __restrict__ beta,
                                                  float* __restrict__ out) {
    __shared__ float s_s[NCH], s_t[NCH];
    if (threadIdx.x < NCH) {
        int c = threadIdx.x;
        float m = g_mv[0];
        float v = g_mv[1];
        float w = conv_w[c];
        float s = gamma[c] * w * rsqrtf(fmaf(w * w, v, 1e-5f));
        s_s[c] = s;
        s_t[c] = beta[c] - s * m;   // conv_b cancels in training-mode BN
    }
    __syncthreads();

    int q = blockIdx.x * blockDim.x + threadIdx.x;
    int b = q / N_PTS, n = q % N_PTS;
    float dmax = g_dmax[q];
#pragma unroll
    for (int c = 0; c < NCH; c++) {
        float s = s_s[c];
        float knn = (s >= 0.f) ? dmax : 0.f;  // min knn = 0 (self-distance)
        float y = fmaf(s, knn, s_t[c]);
        y = (y >= 0.f) ? y : 0.2f * y;        // LeakyReLU commutes with max_k
        out[((size_t)b * NCH + c) * N_PTS + n] = y;
    }
}

extern "C" void kernel_launch(void* const* d_in, const int* in_sizes, int n_in,
                              void* d_out, int out_size) {
    const float* x      = (const float*)d_in[0];
    const float* conv_w = (const float*)d_in[1];
    const float* gamma  = (const float*)d_in[3];
    const float* beta   = (const float*)d_in[4];
    float* out = (float*)d_out;

    knn_kernel<<<NBLK, THREADS>>>(x);
    stats_kernel<<<1, 128>>>();
    out_kernel<<<(B_SZ * N_PTS) / 256, 256>>>(conv_w, gamma, beta, out);
}

// round 8
// speedup vs baseline: 1.1424x; 1.0819x over previous
#include <cuda_runtime.h>
#include <math.h>

#define B_SZ 4
#define N_PTS 8192
#define KNN 20
#define NCH 16
#define TILE 1024
#define THREADS 128
#define SPLIT 4                            // one split per warp
#define QPB 32                             // queries per block (= lane)
#define DQ 24                              // per-lane buffer depth
#define NBLK ((B_SZ * N_PTS) / QPB)        // 1024 knn blocks

__device__ float  g_dmax[B_SZ * N_PTS];
__device__ double g_p1[NBLK];
__device__ double g_p2[NBLK];
__device__ float  g_mv[2];

__device__ __forceinline__ void insert1(float (&r)[KNN], float v) {
#pragma unroll
    for (int k = KNN - 1; k >= 1; k--)
        r[k] = fminf(r[k], fmaxf(r[k - 1], v));
    r[0] = fminf(r[0], v);
}

__device__ __forceinline__ void drain_buf(float (&r)[KNN], const float* mybuf,
                                          int& cnt, float& r19) {
    const float INF = __int_as_float(0x7f800000);
    int jmax = (int)__reduce_max_sync(0xffffffffu, (unsigned)cnt);
    for (int j = 0; j < jmax; j++) {            // warp-uniform loop
        float v = mybuf[j * 32];                // lane-strided: conflict-free
        v = (j < cnt) ? v : INF;
        insert1(r, v);
    }
    cnt = 0;
    r19 = r[KNN - 1];
}

__global__ __launch_bounds__(THREADS, 7) void knn_kernel(const float* __restrict__ x) {
    __shared__ float4 sh[TILE];                       // 16 KB
    __shared__ float  buf[(THREADS / 32) * 32 * DQ];  // 12 KB; reused for merge

    const int warp = threadIdx.x >> 5, lane = threadIdx.x & 31;
    float* mybuf = buf + warp * 32 * DQ + lane;       // slot j -> mybuf[j*32]

    const int ql = lane;                              // local query 0..31
    const int s  = warp;                              // split 0..3

    const int blocks_per_batch = N_PTS / QPB;         // 256
    const int b = blockIdx.x / blocks_per_batch;
    const int n = (blockIdx.x % blocks_per_batch) * QPB + ql;

    const float* xb = x + (size_t)b * 3 * N_PTS;
    const float qx = xb[n];
    const float qy = xb[N_PTS + n];
    const float qz = xb[2 * N_PTS + n];
    const float qsq = fmaf(qx, qx, fmaf(qy, qy, qz * qz));

    // top-20 in e-space: e = |p|^2 - 2 q.p = d2 - qsq (order-preserving)
    const float INF = __int_as_float(0x7f800000);
    float r[KNN];
#pragma unroll
    for (int k = 0; k < KNN; k++) r[k] = INF;
    float r19 = INF;   // stale threshold, refreshed at drains (conservative)
    int cnt = 0;

    for (int t = 0; t < N_PTS; t += TILE) {
        __syncthreads();
        for (int i = threadIdx.x; i < TILE; i += THREADS) {
            float px = xb[t + i];
            float py = xb[N_PTS + t + i];
            float pz = xb[2 * N_PTS + t + i];
            float psq = fmaf(px, px, fmaf(py, py, pz * pz));
            sh[i] = make_float4(-2.f * px, -2.f * py, -2.f * pz, psq);
        }
        __syncthreads();

        const float4* shs = sh + s;        // split s scans i ≡ s (mod 4)
        int jstart = 0;
        if (t == 0) {
            // seed: first 32 candidates inserted unconditionally -> real r19
            for (int j = 0; j < 32; j++) {
                float4 p = shs[j << 2];
                float e = fmaf(qx, p.x, fmaf(qy, p.y, fmaf(qz, p.z, p.w)));
                insert1(r, e);
            }
            r19 = r[KNN - 1];
            jstart = 32;
        }
        for (int j = jstart; j < TILE / SPLIT; j += 8) {
            if (__any_sync(0xffffffffu, cnt >= DQ - 8))
                drain_buf(r, mybuf, cnt, r19);
#pragma unroll
            for (int u = 0; u < 8; u++) {
                float4 p = shs[(j + u) << 2];   // warp-uniform -> broadcast
                float e = fmaf(qx, p.x, fmaf(qy, p.y, fmaf(qz, p.z, p.w)));
                bool q = e < r19;
                mybuf[cnt * 32] = e;      // unconditional; commits only if q
                cnt += (int)q;
            }
        }
    }
    drain_buf(r, mybuf, cnt, r19);        // tail drain

    // ---- merge the 4 split lists per query (exact top-20 of union) ----
    __syncthreads();                       // buf now free -> merge storage
    float* mbuf = buf;                     // [(s-1)*32 + ql]*21 + k (pad 21)
    if (s >= 1) {
#pragma unroll
        for (int k = 0; k < KNN; k++)
            mbuf[((s - 1) * QPB + ql) * 21 + k] = r[k];
    }
    __syncthreads();

    if (s == 0) {
        for (int m = 0; m < SPLIT - 1; m++)
#pragma unroll
            for (int k = 0; k < KNN; k++)
                insert1(r, mbuf[(m * QPB + ql) * 21 + k]);

        // finalize: back to d2-space, clamp, sqrt, stats in double
        double s1 = 0.0, s2 = 0.0;
#pragma unroll
        for (int k = 0; k < KNN; k++) {
            float d2 = fmaxf(r[k] + qsq, 0.f);
            float d = sqrtf(d2);
            s1 += (double)d;
            s2 += (double)d2;
        }
        g_dmax[b * N_PTS + n] = sqrtf(fmaxf(r[KNN - 1] + qsq, 0.f));

#pragma unroll
        for (int o = 16; o > 0; o >>= 1) {
            s1 += __shfl_xor_sync(0xffffffffu, s1, o);
            s2 += __shfl_xor_sync(0xffffffffu, s2, o);
        }
        if (lane == 0) {
            g_p1[blockIdx.x] = s1;
            g_p2[blockIdx.x] = s2;
        }
    }
}

__global__ void stats_kernel() {
    __shared__ double sr1[4], sr2[4];
    int t = threadIdx.x;
    double v1 = 0.0, v2 = 0.0;
#pragma unroll
    for (int i = 0; i < NBLK / 128; i++) {
        v1 += g_p1[t + i * 128];
        v2 += g_p2[t + i * 128];
    }
#pragma unroll
    for (int o = 16; o > 0; o >>= 1) {
        v1 += __shfl_xor_sync(0xffffffffu, v1, o);
        v2 += __shfl_xor_sync(0xffffffffu, v2, o);
    }
    if ((t & 31) == 0) { sr1[t >> 5] = v1; sr2[t >> 5] = v2; }
    __syncthreads();
    if (t == 0) {
        double s1 = sr1[0] + sr1[1] + sr1[2] + sr1[3];
        double s2 = sr2[0] + sr2[1] + sr2[2] + sr2[3];
        const double M = (double)(B_SZ * N_PTS * KNN);
        double m = s1 / M;
        double var = s2 / M - m * m;
        if (var < 0.0) var = 0.0;
        g_mv[0] = (float)m;
        g_mv[1] = (float)var;
    }
}

__global__ __launch_bounds__(256) void out_kernel(const float* __restrict__ conv_w,
                                                  const float* __restrict__ gamma,
                                                  const float* __restrict__ beta,
                                                  float* __restrict__ out) {
    __shared__ float s_s[NCH], s_t[NCH];
    if (threadIdx.x < NCH) {
        int c = threadIdx.x;
        float m = g_mv[0];
        float v = g_mv[1];
        float w = conv_w[c];
        float s = gamma[c] * w * rsqrtf(fmaf(w * w, v, 1e-5f));
        s_s[c] = s;
        s_t[c] = beta[c] - s * m;   // conv_b cancels in training-mode BN
    }
    __syncthreads();

    int q = blockIdx.x * blockDim.x + threadIdx.x;
    int b = q / N_PTS, n = q % N_PTS;
    float dmax = g_dmax[q];
#pragma unroll
    for (int c = 0; c < NCH; c++) {
        float s = s_s[c];
        float knn = (s >= 0.f) ? dmax : 0.f;  // min knn = 0 (self-distance)
        float y = fmaf(s, knn, s_t[c]);
        y = (y >= 0.f) ? y : 0.2f * y;        // LeakyReLU commutes with max_k
        out[((size_t)b * NCH + c) * N_PTS + n] = y;
    }
}

extern "C" void kernel_launch(void* const* d_in, const int* in_sizes, int n_in,
                              void* d_out, int out_size) {
    const float* x      = (const float*)d_in[0];
    const float* conv_w = (const float*)d_in[1];
    const float* gamma  = (const float*)d_in[3];
    const float* beta   = (const float*)d_in[4];
    float* out = (float*)d_out;

    knn_kernel<<<NBLK, THREADS>>>(x);
    stats_kernel<<<1, 128>>>();
    out_kernel<<<(B_SZ * N_PTS) / 256, 256>>>(conv_w, gamma, beta, out);
}